// round 1
// baseline (speedup 1.0000x reference)
#include <cuda_runtime.h>
#include <cstdint>

#define B_  64
#define T_  4096
#define E_  512
#define A_  256

// scratch (allocation-free): decoder projection + context partials
__device__ float g_dproj[B_ * A_];              // 64KB
__device__ float g_cpart[8 * B_ * E_];          // 1MB

// ---------------------------------------------------------------------------
// K0: dproj[b][a] = sum_e dec[b][e] * W_dec[e][a] + b_enc[a]
// ---------------------------------------------------------------------------
__global__ void dproj_kernel(const float* __restrict__ dec,
                             const float* __restrict__ Wd,
                             const float* __restrict__ b_enc) {
    int b = blockIdx.x;
    int a = threadIdx.x;            // 256 threads
    const float* d = dec + b * E_;
    float s = b_enc[a];
    #pragma unroll 8
    for (int e = 0; e < E_; ++e)
        s = fmaf(d[e], Wd[e * A_ + a], s);
    g_dproj[b * A_ + a] = s;
}

// ---------------------------------------------------------------------------
// K1: fused scores. Block = 64 t-rows of one batch, full A=256.
// 256 threads as 16x16; each thread owns 4 rows x 16 cols of the proj tile.
// Epilogue: tanh + dot(v_att) + row-reduce -> scores (pre-softmax) in d_out.
// ---------------------------------------------------------------------------
#define TM 64
#define TK 32

__global__ void __launch_bounds__(256, 2)
scores_kernel(const float* __restrict__ X,       // (B,T,E)
              const float* __restrict__ W,       // (E,A)
              const float* __restrict__ v_att,   // (A)
              const float* __restrict__ b_att,   // scalar
              float* __restrict__ scores)        // (B,T) slice of d_out
{
    __shared__ float Xs[TM][TK + 1];
    __shared__ float Ws[TK][A_];
    __shared__ float red[TM][17];

    const int b   = blockIdx.y;
    const int t0  = blockIdx.x * TM;
    const int tid = threadIdx.x;
    const int ty  = tid >> 4;
    const int tx  = tid & 15;
    const int row0 = ty << 2;

    float acc[4][16];
    #pragma unroll
    for (int r = 0; r < 4; ++r)
        #pragma unroll
        for (int c = 0; c < 16; ++c) acc[r][c] = 0.f;

    const float* Xbase = X + ((size_t)b * T_ + t0) * E_;

    for (int kc = 0; kc < E_; kc += TK) {
        // load X tile: 64 rows x 32 floats (float4 x 2 per thread)
        {
            int idx = tid;
            #pragma unroll
            for (int it = 0; it < 2; ++it) {
                int r  = idx >> 3;
                int c4 = (idx & 7) << 2;
                float4 vx = *(const float4*)(Xbase + (size_t)r * E_ + kc + c4);
                Xs[r][c4 + 0] = vx.x;
                Xs[r][c4 + 1] = vx.y;
                Xs[r][c4 + 2] = vx.z;
                Xs[r][c4 + 3] = vx.w;
                idx += 256;
            }
        }
        // load W tile: 32 x 256 (float4 x 8 per thread)
        {
            #pragma unroll
            for (int it = 0; it < 8; ++it) {
                int idx = tid + (it << 8);
                int r   = idx >> 6;
                int c4  = (idx & 63) << 2;
                *(float4*)&Ws[r][c4] =
                    *(const float4*)(W + (size_t)(kc + r) * A_ + c4);
            }
        }
        __syncthreads();

        #pragma unroll
        for (int k = 0; k < TK; ++k) {
            float a0 = Xs[row0 + 0][k];
            float a1 = Xs[row0 + 1][k];
            float a2 = Xs[row0 + 2][k];
            float a3 = Xs[row0 + 3][k];
            float bf[16];
            #pragma unroll
            for (int j = 0; j < 4; ++j)
                *(float4*)&bf[j << 2] = *(const float4*)&Ws[k][(tx << 4) + (j << 2)];
            #pragma unroll
            for (int c = 0; c < 16; ++c) {
                acc[0][c] = fmaf(a0, bf[c], acc[0][c]);
                acc[1][c] = fmaf(a1, bf[c], acc[1][c]);
                acc[2][c] = fmaf(a2, bf[c], acc[2][c]);
                acc[3][c] = fmaf(a3, bf[c], acc[3][c]);
            }
        }
        __syncthreads();
    }

    // epilogue: tanh + dot v_att
    float dp[16], vv[16];
    {
        const float* dpp = g_dproj + b * A_ + (tx << 4);
        const float* vp  = v_att + (tx << 4);
        #pragma unroll
        for (int j = 0; j < 4; ++j) {
            *(float4*)&dp[j << 2] = *(const float4*)(dpp + (j << 2));
            *(float4*)&vv[j << 2] = *(const float4*)(vp + (j << 2));
        }
    }
    #pragma unroll
    for (int r = 0; r < 4; ++r) {
        float s = 0.f;
        #pragma unroll
        for (int c = 0; c < 16; ++c)
            s = fmaf(vv[c], tanhf(acc[r][c] + dp[c]), s);
        red[row0 + r][tx] = s;
    }
    __syncthreads();

    if (tid < TM) {
        float s = b_att[0];
        #pragma unroll
        for (int c = 0; c < 16; ++c) s += red[tid][c];
        scores[(size_t)b * T_ + t0 + tid] = s;
    }
}

// ---------------------------------------------------------------------------
// K2: in-place softmax over T per batch. 1024 threads, 4 elems/thread.
// ---------------------------------------------------------------------------
__global__ void softmax_kernel(float* __restrict__ w) {
    const int b   = blockIdx.x;
    float* row    = w + (size_t)b * T_;
    const int tid = threadIdx.x;       // 1024
    const int lane = tid & 31, wid = tid >> 5;

    __shared__ float sm[32];
    __shared__ float s_bcast;

    float v[4];
    float m = -1e30f;
    #pragma unroll
    for (int i = 0; i < 4; ++i) {
        v[i] = row[tid + (i << 10)];
        m = fmaxf(m, v[i]);
    }
    #pragma unroll
    for (int o = 16; o; o >>= 1) m = fmaxf(m, __shfl_xor_sync(0xffffffffu, m, o));
    if (lane == 0) sm[wid] = m;
    __syncthreads();
    if (tid < 32) {
        float t = sm[tid];
        #pragma unroll
        for (int o = 16; o; o >>= 1) t = fmaxf(t, __shfl_xor_sync(0xffffffffu, t, o));
        if (tid == 0) s_bcast = t;
    }
    __syncthreads();
    const float mx = s_bcast;

    float s = 0.f;
    #pragma unroll
    for (int i = 0; i < 4; ++i) {
        v[i] = __expf(v[i] - mx);
        s += v[i];
    }
    #pragma unroll
    for (int o = 16; o; o >>= 1) s += __shfl_xor_sync(0xffffffffu, s, o);
    if (lane == 0) sm[wid] = s;
    __syncthreads();
    if (tid < 32) {
        float t = sm[tid];
        #pragma unroll
        for (int o = 16; o; o >>= 1) t += __shfl_xor_sync(0xffffffffu, t, o);
        if (tid == 0) s_bcast = t;
    }
    __syncthreads();
    const float inv = 1.0f / s_bcast;

    #pragma unroll
    for (int i = 0; i < 4; ++i)
        row[tid + (i << 10)] = v[i] * inv;
}

// ---------------------------------------------------------------------------
// K3: context partials. grid (8, B); thread e accumulates 512 t's.
// ---------------------------------------------------------------------------
__global__ void cpart_kernel(const float* __restrict__ X,
                             const float* __restrict__ w) {
    const int c = blockIdx.x;          // 0..7
    const int b = blockIdx.y;
    const int e = threadIdx.x;         // 512
    const float* xb = X + ((size_t)b * T_ + (size_t)c * 512) * E_ + e;
    const float* wb = w + (size_t)b * T_ + (size_t)c * 512;

    float a0 = 0.f, a1 = 0.f, a2 = 0.f, a3 = 0.f;
    #pragma unroll 4
    for (int t = 0; t < 512; t += 4) {
        a0 = fmaf(wb[t + 0], xb[(size_t)(t + 0) * E_], a0);
        a1 = fmaf(wb[t + 1], xb[(size_t)(t + 1) * E_], a1);
        a2 = fmaf(wb[t + 2], xb[(size_t)(t + 2) * E_], a2);
        a3 = fmaf(wb[t + 3], xb[(size_t)(t + 3) * E_], a3);
    }
    g_cpart[((size_t)c * B_ + b) * E_ + e] = (a0 + a1) + (a2 + a3);
}

// ---------------------------------------------------------------------------
// K4: reduce partials -> context in d_out
// ---------------------------------------------------------------------------
__global__ void creduce_kernel(float* __restrict__ ctx) {
    int i = blockIdx.x * blockDim.x + threadIdx.x;   // 32768
    int b = i >> 9, e = i & 511;
    float s = 0.f;
    #pragma unroll
    for (int c = 0; c < 8; ++c)
        s += g_cpart[((size_t)c * B_ + b) * E_ + e];
    ctx[i] = s;
}

// ---------------------------------------------------------------------------
extern "C" void kernel_launch(void* const* d_in, const int* in_sizes, int n_in,
                              void* d_out, int out_size) {
    const float* X     = (const float*)d_in[0];   // (B,T,E)
    const float* dec   = (const float*)d_in[1];   // (B,DEC)
    const float* W_enc = (const float*)d_in[2];   // (E,A)
    const float* b_enc = (const float*)d_in[3];   // (A)
    const float* W_dec = (const float*)d_in[4];   // (DEC,A)
    const float* v_att = (const float*)d_in[5];   // (A)
    const float* b_att = (const float*)d_in[6];   // ()

    float* ctx     = (float*)d_out;               // (B,E)
    float* weights = (float*)d_out + B_ * E_;     // (B,T)

    dproj_kernel<<<B_, A_>>>(dec, W_dec, b_enc);

    dim3 g1(T_ / TM, B_);
    scores_kernel<<<g1, 256>>>(X, W_enc, v_att, b_att, weights);

    softmax_kernel<<<B_, 1024>>>(weights);

    dim3 g3(8, B_);
    cpart_kernel<<<g3, E_>>>(X, weights);

    creduce_kernel<<<(B_ * E_) / 256, 256>>>(ctx);
}

// round 3
// speedup vs baseline: 4.4722x; 4.4722x over previous
#include <cuda_runtime.h>
#include <cuda_bf16.h>
#include <cstdint>

#define B_  64
#define T_  4096
#define E_  512
#define A_  256

// ---------------------------------------------------------------------------
// scratch (allocation-free)
// ---------------------------------------------------------------------------
__device__ float g_dproj[B_ * A_];
__device__ float g_cpart[8 * B_ * E_];
__device__ __align__(128) __nv_bfloat16 g_Xh[(size_t)B_ * T_ * E_];
__device__ __align__(128) __nv_bfloat16 g_Xl[(size_t)B_ * T_ * E_];
__device__ __align__(128) __nv_bfloat16 g_Wh[A_ * E_];   // [n][k] K-major
__device__ __align__(128) __nv_bfloat16 g_Wl[A_ * E_];

// ---------------------------------------------------------------------------
// helpers
// ---------------------------------------------------------------------------
__device__ __forceinline__ uint32_t smem_u32(const void* p) {
    uint32_t a;
    asm("{ .reg .u64 t; cvta.to.shared.u64 t, %1; cvt.u32.u64 %0, t; }" : "=r"(a) : "l"(p));
    return a;
}
__device__ __forceinline__ uint32_t swz64(uint32_t o) { return o ^ ((o >> 3) & 0x30); }

#define CP_ASYNC16(dst, src) \
    asm volatile("cp.async.cg.shared.global [%0], [%1], 16;" :: "r"(dst), "l"(src) : "memory")
#define CP_COMMIT()  asm volatile("cp.async.commit_group;" ::: "memory")
#define CP_WAIT1()   asm volatile("cp.async.wait_group 1;" ::: "memory")
#define CP_WAIT0()   asm volatile("cp.async.wait_group 0;" ::: "memory")

#define LDM4(r, a) \
    asm volatile("ldmatrix.sync.aligned.m8n8.x4.shared.b16 {%0,%1,%2,%3}, [%4];" \
        : "=r"((r)[0]), "=r"((r)[1]), "=r"((r)[2]), "=r"((r)[3]) : "r"(a))

__device__ __forceinline__ void mma_bf16(float* c, const uint32_t* a, const uint32_t* b) {
    asm volatile(
        "mma.sync.aligned.m16n8k16.row.col.f32.bf16.bf16.f32 "
        "{%0,%1,%2,%3}, {%4,%5,%6,%7}, {%8,%9}, {%0,%1,%2,%3};"
        : "+f"(c[0]), "+f"(c[1]), "+f"(c[2]), "+f"(c[3])
        : "r"(a[0]), "r"(a[1]), "r"(a[2]), "r"(a[3]), "r"(b[0]), "r"(b[1]));
}

// ---------------------------------------------------------------------------
// converts
// ---------------------------------------------------------------------------
__global__ void convert_x_kernel(const float* __restrict__ X) {
    size_t i = ((size_t)blockIdx.x * 256 + threadIdx.x) * 4;
    float4 v = *(const float4*)(X + i);
    __nv_bfloat16 h0 = __float2bfloat16_rn(v.x);
    __nv_bfloat16 h1 = __float2bfloat16_rn(v.y);
    __nv_bfloat16 h2 = __float2bfloat16_rn(v.z);
    __nv_bfloat16 h3 = __float2bfloat16_rn(v.w);
    ushort4 hv = { __bfloat16_as_ushort(h0), __bfloat16_as_ushort(h1),
                   __bfloat16_as_ushort(h2), __bfloat16_as_ushort(h3) };
    ushort4 lv = {
        __bfloat16_as_ushort(__float2bfloat16_rn(v.x - __bfloat162float(h0))),
        __bfloat16_as_ushort(__float2bfloat16_rn(v.y - __bfloat162float(h1))),
        __bfloat16_as_ushort(__float2bfloat16_rn(v.z - __bfloat162float(h2))),
        __bfloat16_as_ushort(__float2bfloat16_rn(v.w - __bfloat162float(h3))) };
    *(ushort4*)(&g_Xh[i]) = hv;
    *(ushort4*)(&g_Xl[i]) = lv;
}

__global__ void convert_w_kernel(const float* __restrict__ W) {
    int k = blockIdx.x;     // 512
    int n = threadIdx.x;    // 256
    float w = W[k * A_ + n];
    __nv_bfloat16 h = __float2bfloat16_rn(w);
    g_Wh[n * E_ + k] = h;
    g_Wl[n * E_ + k] = __float2bfloat16_rn(w - __bfloat162float(h));
}

__global__ void dproj_kernel(const float* __restrict__ dec,
                             const float* __restrict__ Wd,
                             const float* __restrict__ b_enc) {
    int b = blockIdx.x;
    int a = threadIdx.x;
    const float* d = dec + b * E_;
    float s = b_enc[a];
    #pragma unroll 8
    for (int e = 0; e < E_; ++e)
        s = fmaf(d[e], Wd[e * A_ + a], s);
    g_dproj[b * A_ + a] = s;
}

// ---------------------------------------------------------------------------
// K1: HMMA scores GEMM. CTA: M=128 x N=256, K=512 (16 chunks of 32).
// 8 warps (2M x 4N), warp tile 64x64, 3-term bf16 split, cp.async dbl-buffer.
// smem stage: XH 8K | XL 8K | WH 16K | WL 16K = 48K, two stages.
// ---------------------------------------------------------------------------
#define KC       32
#define NCH      16
#define STAGE_SZ 49152
#define OFF_V    98304
#define OFF_DP   99328
#define OFF_RED  100352
#define SMEM_TOTAL 102400

__global__ void __launch_bounds__(256, 1)
scores_mma_kernel(const float* __restrict__ v_att,
                  const float* __restrict__ b_att,
                  float* __restrict__ scores)
{
    extern __shared__ char smem[];
    const uint32_t sb = smem_u32(smem);
    const int tid = threadIdx.x;
    const int lane = tid & 31, wid = tid >> 5;
    const int wm = wid >> 2, wn = wid & 3;
    const int b = blockIdx.y;
    const int t0 = blockIdx.x * 128;

    float* vs  = (float*)(smem + OFF_V);
    float* dps = (float*)(smem + OFF_DP);
    float* red = (float*)(smem + OFF_RED);
    vs[tid]  = v_att[tid];
    dps[tid] = g_dproj[b * A_ + tid];

    const __nv_bfloat16* xh = g_Xh + ((size_t)b * T_ + t0) * E_;
    const __nv_bfloat16* xl = g_Xl + ((size_t)b * T_ + t0) * E_;

    float acc[4][8][4];
    #pragma unroll
    for (int mt = 0; mt < 4; ++mt)
        #pragma unroll
        for (int nt = 0; nt < 8; ++nt)
            #pragma unroll
            for (int e = 0; e < 4; ++e) acc[mt][nt][e] = 0.f;

    // per-lane ldmatrix row offsets (unswizzled)
    const int rsel = lane & 15, chalf = lane >> 4;
    uint32_t arow[4], brow[4];
    #pragma unroll
    for (int mt = 0; mt < 4; ++mt)
        arow[mt] = (uint32_t)(((wm << 6) + (mt << 4) + rsel) << 6) + (chalf << 4);
    #pragma unroll
    for (int nt2 = 0; nt2 < 4; ++nt2)
        brow[nt2] = (uint32_t)(((wn << 6) + (nt2 << 4) + rsel) << 6) + (chalf << 4);

    // chunk loader
    auto load_chunk = [&](int c) {
        const int kc = c * KC;
        const uint32_t st = sb + (uint32_t)(c & 1) * STAGE_SZ;
        #pragma unroll
        for (int it = 0; it < 4; ++it) {           // X: 1024 granules of 16B
            int i = tid + (it << 8);
            int sp = i >> 9, r = (i >> 2) & 127, q = i & 3;
            const __nv_bfloat16* src = (sp ? xl : xh) + (size_t)r * E_ + kc + (q << 3);
            uint32_t dst = st + (sp ? 8192u : 0u) + swz64((r << 6) + (q << 4));
            CP_ASYNC16(dst, src);
        }
        #pragma unroll
        for (int it = 0; it < 8; ++it) {           // W: 2048 granules
            int i = tid + (it << 8);
            int sp = i >> 10, r = (i >> 2) & 255, q = i & 3;
            const __nv_bfloat16* src = (sp ? g_Wl : g_Wh) + (size_t)r * E_ + kc + (q << 3);
            uint32_t dst = st + 16384u + (sp ? 16384u : 0u) + swz64((r << 6) + (q << 4));
            CP_ASYNC16(dst, src);
        }
        CP_COMMIT();
    };

    load_chunk(0);

    for (int c = 0; c < NCH; ++c) {
        if (c + 1 < NCH) { load_chunk(c + 1); CP_WAIT1(); }
        else             { CP_WAIT0(); }
        __syncthreads();

        const uint32_t st = sb + (uint32_t)(c & 1) * STAGE_SZ;
        #pragma unroll
        for (int ks = 0; ks < 2; ++ks) {
            const uint32_t koff = ks << 5;
            uint32_t Ah[4][4], Al[4][4];
            #pragma unroll
            for (int mt = 0; mt < 4; ++mt) {
                LDM4(Ah[mt], st + swz64(arow[mt] + koff));
                LDM4(Al[mt], st + 8192u + swz64(arow[mt] + koff));
            }
            #pragma unroll
            for (int nt2 = 0; nt2 < 4; ++nt2) {
                uint32_t Bh[4], Bl[4];
                LDM4(Bh, st + 16384u + swz64(brow[nt2] + koff));
                LDM4(Bl, st + 32768u + swz64(brow[nt2] + koff));
                uint32_t bhe[2] = { Bh[0], Bh[2] }, bho[2] = { Bh[1], Bh[3] };
                uint32_t ble[2] = { Bl[0], Bl[2] }, blo[2] = { Bl[1], Bl[3] };
                #pragma unroll
                for (int mt = 0; mt < 4; ++mt) {
                    mma_bf16(acc[mt][nt2 * 2],     Ah[mt], bhe);
                    mma_bf16(acc[mt][nt2 * 2 + 1], Ah[mt], bho);
                    mma_bf16(acc[mt][nt2 * 2],     Ah[mt], ble);
                    mma_bf16(acc[mt][nt2 * 2 + 1], Ah[mt], blo);
                    mma_bf16(acc[mt][nt2 * 2],     Al[mt], bhe);
                    mma_bf16(acc[mt][nt2 * 2 + 1], Al[mt], bho);
                }
            }
        }
        __syncthreads();
    }

    // epilogue: tanh + v dot, reduce within warp quads, then across wn
    const int g = lane >> 2, t = lane & 3;
    #pragma unroll
    for (int mt = 0; mt < 4; ++mt) {
        float pa = 0.f, pb = 0.f;
        #pragma unroll
        for (int nt = 0; nt < 8; ++nt) {
            int col = (wn << 6) + (nt << 3) + (t << 1);
            float v0 = vs[col], v1 = vs[col + 1];
            float d0 = dps[col], d1 = dps[col + 1];
            pa = fmaf(v0, tanhf(acc[mt][nt][0] + d0), pa);
            pa = fmaf(v1, tanhf(acc[mt][nt][1] + d1), pa);
            pb = fmaf(v0, tanhf(acc[mt][nt][2] + d0), pb);
            pb = fmaf(v1, tanhf(acc[mt][nt][3] + d1), pb);
        }
        pa += __shfl_xor_sync(0xffffffffu, pa, 1);
        pa += __shfl_xor_sync(0xffffffffu, pa, 2);
        pb += __shfl_xor_sync(0xffffffffu, pb, 1);
        pb += __shfl_xor_sync(0xffffffffu, pb, 2);
        if (t == 0) {
            int row = (wm << 6) + (mt << 4) + g;
            red[row * 4 + wn]       = pa;
            red[(row + 8) * 4 + wn] = pb;
        }
    }
    __syncthreads();

    if (tid < 128) {
        float s = red[tid * 4] + red[tid * 4 + 1] + red[tid * 4 + 2] + red[tid * 4 + 3];
        scores[(size_t)b * T_ + t0 + tid] = s + b_att[0];
    }
}

// ---------------------------------------------------------------------------
// K2: softmax over T per batch
// ---------------------------------------------------------------------------
__global__ void softmax_kernel(float* __restrict__ w) {
    const int b = blockIdx.x;
    float* row = w + (size_t)b * T_;
    const int tid = threadIdx.x, lane = tid & 31, wd = tid >> 5;
    __shared__ float sm[32];
    __shared__ float s_b;

    float v[4];
    float m = -1e30f;
    #pragma unroll
    for (int i = 0; i < 4; ++i) { v[i] = row[tid + (i << 10)]; m = fmaxf(m, v[i]); }
    #pragma unroll
    for (int o = 16; o; o >>= 1) m = fmaxf(m, __shfl_xor_sync(0xffffffffu, m, o));
    if (lane == 0) sm[wd] = m;
    __syncthreads();
    if (tid < 32) {
        float t = sm[tid];
        #pragma unroll
        for (int o = 16; o; o >>= 1) t = fmaxf(t, __shfl_xor_sync(0xffffffffu, t, o));
        if (tid == 0) s_b = t;
    }
    __syncthreads();
    const float mx = s_b;

    float s = 0.f;
    #pragma unroll
    for (int i = 0; i < 4; ++i) { v[i] = __expf(v[i] - mx); s += v[i]; }
    #pragma unroll
    for (int o = 16; o; o >>= 1) s += __shfl_xor_sync(0xffffffffu, s, o);
    if (lane == 0) sm[wd] = s;
    __syncthreads();
    if (tid < 32) {
        float t = sm[tid];
        #pragma unroll
        for (int o = 16; o; o >>= 1) t += __shfl_xor_sync(0xffffffffu, t, o);
        if (tid == 0) s_b = t;
    }
    __syncthreads();
    const float inv = 1.0f / s_b;
    #pragma unroll
    for (int i = 0; i < 4; ++i) row[tid + (i << 10)] = v[i] * inv;
}

// ---------------------------------------------------------------------------
// K3/K4: context
// ---------------------------------------------------------------------------
__global__ void cpart_kernel(const float* __restrict__ X,
                             const float* __restrict__ w) {
    const int c = blockIdx.x, b = blockIdx.y, e = threadIdx.x;
    const float* xb = X + ((size_t)b * T_ + (size_t)c * 512) * E_ + e;
    const float* wb = w + (size_t)b * T_ + (size_t)c * 512;
    float a[8] = {0,0,0,0,0,0,0,0};
    #pragma unroll 2
    for (int t = 0; t < 512; t += 8) {
        #pragma unroll
        for (int u = 0; u < 8; ++u)
            a[u] = fmaf(wb[t + u], xb[(size_t)(t + u) * E_], a[u]);
    }
    g_cpart[((size_t)c * B_ + b) * E_ + e] =
        ((a[0] + a[1]) + (a[2] + a[3])) + ((a[4] + a[5]) + (a[6] + a[7]));
}

__global__ void creduce_kernel(float* __restrict__ ctx) {
    int i = blockIdx.x * blockDim.x + threadIdx.x;
    int b = i >> 9, e = i & 511;
    float s = 0.f;
    #pragma unroll
    for (int c = 0; c < 8; ++c)
        s += g_cpart[((size_t)c * B_ + b) * E_ + e];
    ctx[i] = s;
}

// ---------------------------------------------------------------------------
extern "C" void kernel_launch(void* const* d_in, const int* in_sizes, int n_in,
                              void* d_out, int out_size) {
    const float* X     = (const float*)d_in[0];
    const float* dec   = (const float*)d_in[1];
    const float* W_enc = (const float*)d_in[2];
    const float* b_enc = (const float*)d_in[3];
    const float* W_dec = (const float*)d_in[4];
    const float* v_att = (const float*)d_in[5];
    const float* b_att = (const float*)d_in[6];

    float* ctx     = (float*)d_out;
    float* weights = (float*)d_out + B_ * E_;

    cudaFuncSetAttribute(scores_mma_kernel,
                         cudaFuncAttributeMaxDynamicSharedMemorySize, SMEM_TOTAL);

    convert_x_kernel<<<(size_t)B_ * T_ * E_ / 4 / 256, 256>>>(X);
    convert_w_kernel<<<E_, A_>>>(W_enc);
    dproj_kernel<<<B_, A_>>>(dec, W_dec, b_enc);

    dim3 g1(T_ / 128, B_);
    scores_mma_kernel<<<g1, 256, SMEM_TOTAL>>>(v_att, b_att, weights);

    softmax_kernel<<<B_, 1024>>>(weights);

    dim3 g3(8, B_);
    cpart_kernel<<<g3, E_>>>(X, weights);
    creduce_kernel<<<(B_ * E_) / 256, 256>>>(ctx);
}

// round 4
// speedup vs baseline: 4.8541x; 1.0854x over previous
#include <cuda_runtime.h>
#include <cuda_bf16.h>
#include <cstdint>

#define B_  64
#define T_  4096
#define E_  512
#define A_  256

// ---------------------------------------------------------------------------
// scratch (allocation-free)
// ---------------------------------------------------------------------------
__device__ float g_dproj[B_ * A_];
__device__ float g_cpart[8 * B_ * E_];
__device__ __align__(128) __nv_bfloat16 g_Wh[A_ * E_];   // [n][k] K-major
__device__ __align__(128) __nv_bfloat16 g_Wl[A_ * E_];

// ---------------------------------------------------------------------------
// helpers
// ---------------------------------------------------------------------------
__device__ __forceinline__ uint32_t smem_u32(const void* p) {
    uint32_t a;
    asm("{ .reg .u64 t; cvta.to.shared.u64 t, %1; cvt.u32.u64 %0, t; }" : "=r"(a) : "l"(p));
    return a;
}
__device__ __forceinline__ uint32_t swz64(uint32_t o) { return o ^ ((o >> 3) & 0x30); }

#define CP_ASYNC16(dst, src) \
    asm volatile("cp.async.cg.shared.global [%0], [%1], 16;" :: "r"(dst), "l"(src) : "memory")
#define CP_COMMIT()  asm volatile("cp.async.commit_group;" ::: "memory")
#define CP_WAIT1()   asm volatile("cp.async.wait_group 1;" ::: "memory")
#define CP_WAIT0()   asm volatile("cp.async.wait_group 0;" ::: "memory")

#define LDM4(r, a) \
    asm volatile("ldmatrix.sync.aligned.m8n8.x4.shared.b16 {%0,%1,%2,%3}, [%4];" \
        : "=r"((r)[0]), "=r"((r)[1]), "=r"((r)[2]), "=r"((r)[3]) : "r"(a))

__device__ __forceinline__ void mma_bf16(float* c, const uint32_t* a, const uint32_t* b) {
    asm volatile(
        "mma.sync.aligned.m16n8k16.row.col.f32.bf16.bf16.f32 "
        "{%0,%1,%2,%3}, {%4,%5,%6,%7}, {%8,%9}, {%0,%1,%2,%3};"
        : "+f"(c[0]), "+f"(c[1]), "+f"(c[2]), "+f"(c[3])
        : "r"(a[0]), "r"(a[1]), "r"(a[2]), "r"(a[3]), "r"(b[0]), "r"(b[1]));
}

// ---------------------------------------------------------------------------
// small prep kernels
// ---------------------------------------------------------------------------
__global__ void convert_w_kernel(const float* __restrict__ W) {
    int k = blockIdx.x;     // 512
    int n = threadIdx.x;    // 256
    float w = W[k * A_ + n];
    __nv_bfloat16 h = __float2bfloat16_rn(w);
    g_Wh[n * E_ + k] = h;
    g_Wl[n * E_ + k] = __float2bfloat16_rn(w - __bfloat162float(h));
}

__global__ void dproj_kernel(const float* __restrict__ dec,
                             const float* __restrict__ Wd,
                             const float* __restrict__ b_enc) {
    int b = blockIdx.x;
    int a = threadIdx.x;
    const float* d = dec + b * E_;
    float s = b_enc[a];
    #pragma unroll 8
    for (int e = 0; e < E_; ++e)
        s = fmaf(d[e], Wd[e * A_ + a], s);
    g_dproj[b * A_ + a] = s;
}

// ---------------------------------------------------------------------------
// K1: HMMA scores GEMM with fused fp32->bf16(hi,lo) split conversion.
// CTA: M=128 x N=256, K=512 (16 chunks of 32). 8 warps (2M x 4N), warp 64x64.
// Pipeline: cp.async fp32 X stage + bf16 W (double-buffered), in-smem convert
// to swizzled bf16 Xh/Xl (single-buffered), MMA term-reordered for ILP.
// ---------------------------------------------------------------------------
#define KC       32
#define NCH      16
#define OFF_XF   0                      // 2 x 16KB fp32 stage
#define OFF_XH   32768                  // 8KB
#define OFF_XL   40960                  // 8KB
#define OFF_WH   49152                  // 2 x 16KB
#define OFF_WL   81920                  // 2 x 16KB
#define OFF_V    114688
#define OFF_DP   115712
#define OFF_RED  116736
#define SMEM_TOTAL 118784

__global__ void __launch_bounds__(256, 1)
scores_mma_kernel(const float* __restrict__ X,
                  const float* __restrict__ v_att,
                  const float* __restrict__ b_att,
                  float* __restrict__ scores)
{
    extern __shared__ char smem[];
    const uint32_t sb = smem_u32(smem);
    const int tid = threadIdx.x;
    const int lane = tid & 31, wid = tid >> 5;
    const int wm = wid >> 2, wn = wid & 3;
    const int b = blockIdx.y;
    const int t0 = blockIdx.x * 128;

    float* vs  = (float*)(smem + OFF_V);
    float* dps = (float*)(smem + OFF_DP);
    float* red = (float*)(smem + OFF_RED);
    vs[tid]  = v_att[tid];
    dps[tid] = g_dproj[b * A_ + tid];

    const float* xrow = X + ((size_t)b * T_ + t0) * E_;

    float acc[4][8][4];
    #pragma unroll
    for (int mt = 0; mt < 4; ++mt)
        #pragma unroll
        for (int nt = 0; nt < 8; ++nt)
            #pragma unroll
            for (int e = 0; e < 4; ++e) acc[mt][nt][e] = 0.f;

    // per-lane ldmatrix row offsets (unswizzled, within 64B-row tiles)
    const int rsel = lane & 15, chalf = lane >> 4;
    uint32_t arow[4], brow[4];
    #pragma unroll
    for (int mt = 0; mt < 4; ++mt)
        arow[mt] = (uint32_t)(((wm << 6) + (mt << 4) + rsel) << 6) + (chalf << 4);
    #pragma unroll
    for (int n2 = 0; n2 < 4; ++n2)
        brow[n2] = (uint32_t)(((wn << 6) + (n2 << 4) + rsel) << 6) + (chalf << 4);

    const uint32_t xh_b = sb + OFF_XH;
    const uint32_t xl_b = sb + OFF_XL;

    // chunk loader: fp32 X tile (128x32) + W hi/lo tiles (256x32 bf16)
    auto load_chunk = [&](int c) {
        const int kc = c * KC;
        const uint32_t s14 = (uint32_t)(c & 1) << 14;
        #pragma unroll
        for (int it = 0; it < 4; ++it) {           // X: 1024 x 16B
            int i = tid + (it << 8);
            int r = i >> 3, q = i & 7;
            const float* src = xrow + (size_t)r * E_ + kc + (q << 2);
            CP_ASYNC16(sb + OFF_XF + s14 + (uint32_t)(i << 4), src);
        }
        #pragma unroll
        for (int it = 0; it < 8; ++it) {           // W: 2048 x 16B
            int i = tid + (it << 8);
            int sp = i >> 10, r = (i >> 2) & 255, q = i & 3;
            const __nv_bfloat16* src = (sp ? g_Wl : g_Wh) + (size_t)r * E_ + kc + (q << 3);
            uint32_t dst = sb + (sp ? OFF_WL : OFF_WH) + s14 + swz64((r << 6) + (q << 4));
            CP_ASYNC16(dst, src);
        }
        CP_COMMIT();
    };

    load_chunk(0);

    for (int c = 0; c < NCH; ++c) {
        if (c + 1 < NCH) { load_chunk(c + 1); CP_WAIT1(); }
        else             { CP_WAIT0(); }
        __syncthreads();                           // chunk c data visible

        // convert fp32 stage -> swizzled bf16 Xh/Xl
        {
            const char* xf = smem + OFF_XF + ((c & 1) << 14);
            #pragma unroll
            for (int it = 0; it < 4; ++it) {
                int g = tid + (it << 8);
                int r = g >> 3, q = g & 7;
                float4 v = *(const float4*)(xf + (g << 4));
                __nv_bfloat16 h0 = __float2bfloat16_rn(v.x);
                __nv_bfloat16 h1 = __float2bfloat16_rn(v.y);
                __nv_bfloat16 h2 = __float2bfloat16_rn(v.z);
                __nv_bfloat16 h3 = __float2bfloat16_rn(v.w);
                uint32_t hi0 = (uint32_t)__bfloat16_as_ushort(h0) |
                               ((uint32_t)__bfloat16_as_ushort(h1) << 16);
                uint32_t hi1 = (uint32_t)__bfloat16_as_ushort(h2) |
                               ((uint32_t)__bfloat16_as_ushort(h3) << 16);
                uint32_t lo0 = (uint32_t)__bfloat16_as_ushort(__float2bfloat16_rn(v.x - __bfloat162float(h0))) |
                               ((uint32_t)__bfloat16_as_ushort(__float2bfloat16_rn(v.y - __bfloat162float(h1))) << 16);
                uint32_t lo1 = (uint32_t)__bfloat16_as_ushort(__float2bfloat16_rn(v.z - __bfloat162float(h2))) |
                               ((uint32_t)__bfloat16_as_ushort(__float2bfloat16_rn(v.w - __bfloat162float(h3))) << 16);
                uint32_t off = swz64((uint32_t)((r << 6) + (q << 3)));
                *(uint2*)(smem + OFF_XH + off) = make_uint2(hi0, hi1);
                *(uint2*)(smem + OFF_XL + off) = make_uint2(lo0, lo1);
            }
        }
        __syncthreads();                           // Xh/Xl ready

        const uint32_t wh = sb + OFF_WH + ((uint32_t)(c & 1) << 14);
        const uint32_t wl = sb + OFF_WL + ((uint32_t)(c & 1) << 14);

        #pragma unroll
        for (int ks = 0; ks < 2; ++ks) {
            const uint32_t koff = ks << 5;
            uint32_t A[4][4], Bf[4][4];

            // term 1: Xh * Wh
            #pragma unroll
            for (int mt = 0; mt < 4; ++mt) LDM4(A[mt], xh_b + swz64(arow[mt] + koff));
            #pragma unroll
            for (int n2 = 0; n2 < 4; ++n2) LDM4(Bf[n2], wh + swz64(brow[n2] + koff));
            #pragma unroll
            for (int n2 = 0; n2 < 4; ++n2) {
                uint32_t be[2] = { Bf[n2][0], Bf[n2][2] };
                uint32_t bo[2] = { Bf[n2][1], Bf[n2][3] };
                #pragma unroll
                for (int mt = 0; mt < 4; ++mt) {
                    mma_bf16(acc[mt][n2 * 2],     A[mt], be);
                    mma_bf16(acc[mt][n2 * 2 + 1], A[mt], bo);
                }
            }
            // term 2: Xh * Wl
            #pragma unroll
            for (int n2 = 0; n2 < 4; ++n2) LDM4(Bf[n2], wl + swz64(brow[n2] + koff));
            #pragma unroll
            for (int n2 = 0; n2 < 4; ++n2) {
                uint32_t be[2] = { Bf[n2][0], Bf[n2][2] };
                uint32_t bo[2] = { Bf[n2][1], Bf[n2][3] };
                #pragma unroll
                for (int mt = 0; mt < 4; ++mt) {
                    mma_bf16(acc[mt][n2 * 2],     A[mt], be);
                    mma_bf16(acc[mt][n2 * 2 + 1], A[mt], bo);
                }
            }
            // term 3: Xl * Wh
            #pragma unroll
            for (int mt = 0; mt < 4; ++mt) LDM4(A[mt], xl_b + swz64(arow[mt] + koff));
            #pragma unroll
            for (int n2 = 0; n2 < 4; ++n2) LDM4(Bf[n2], wh + swz64(brow[n2] + koff));
            #pragma unroll
            for (int n2 = 0; n2 < 4; ++n2) {
                uint32_t be[2] = { Bf[n2][0], Bf[n2][2] };
                uint32_t bo[2] = { Bf[n2][1], Bf[n2][3] };
                #pragma unroll
                for (int mt = 0; mt < 4; ++mt) {
                    mma_bf16(acc[mt][n2 * 2],     A[mt], be);
                    mma_bf16(acc[mt][n2 * 2 + 1], A[mt], bo);
                }
            }
        }
        __syncthreads();                           // done reading stage c
    }

    // epilogue: tanh + v dot, reduce within warp quads, then across wn
    const int g = lane >> 2, t = lane & 3;
    #pragma unroll
    for (int mt = 0; mt < 4; ++mt) {
        float pa = 0.f, pb = 0.f;
        #pragma unroll
        for (int nt = 0; nt < 8; ++nt) {
            int col = (wn << 6) + (nt << 3) + (t << 1);
            float v0 = vs[col], v1 = vs[col + 1];
            float d0 = dps[col], d1 = dps[col + 1];
            pa = fmaf(v0, tanhf(acc[mt][nt][0] + d0), pa);
            pa = fmaf(v1, tanhf(acc[mt][nt][1] + d1), pa);
            pb = fmaf(v0, tanhf(acc[mt][nt][2] + d0), pb);
            pb = fmaf(v1, tanhf(acc[mt][nt][3] + d1), pb);
        }
        pa += __shfl_xor_sync(0xffffffffu, pa, 1);
        pa += __shfl_xor_sync(0xffffffffu, pa, 2);
        pb += __shfl_xor_sync(0xffffffffu, pb, 1);
        pb += __shfl_xor_sync(0xffffffffu, pb, 2);
        if (t == 0) {
            int row = (wm << 6) + (mt << 4) + g;
            red[row * 4 + wn]       = pa;
            red[(row + 8) * 4 + wn] = pb;
        }
    }
    __syncthreads();

    if (tid < 128) {
        float s = red[tid * 4] + red[tid * 4 + 1] + red[tid * 4 + 2] + red[tid * 4 + 3];
        scores[(size_t)b * T_ + t0 + tid] = s + b_att[0];
    }
}

// ---------------------------------------------------------------------------
// K2: softmax over T per batch
// ---------------------------------------------------------------------------
__global__ void softmax_kernel(float* __restrict__ w) {
    const int b = blockIdx.x;
    float* row = w + (size_t)b * T_;
    const int tid = threadIdx.x, lane = tid & 31, wd = tid >> 5;
    __shared__ float sm[32];
    __shared__ float s_b;

    float v[4];
    float m = -1e30f;
    #pragma unroll
    for (int i = 0; i < 4; ++i) { v[i] = row[tid + (i << 10)]; m = fmaxf(m, v[i]); }
    #pragma unroll
    for (int o = 16; o; o >>= 1) m = fmaxf(m, __shfl_xor_sync(0xffffffffu, m, o));
    if (lane == 0) sm[wd] = m;
    __syncthreads();
    if (tid < 32) {
        float t = sm[tid];
        #pragma unroll
        for (int o = 16; o; o >>= 1) t = fmaxf(t, __shfl_xor_sync(0xffffffffu, t, o));
        if (tid == 0) s_b = t;
    }
    __syncthreads();
    const float mx = s_b;

    float s = 0.f;
    #pragma unroll
    for (int i = 0; i < 4; ++i) { v[i] = __expf(v[i] - mx); s += v[i]; }
    #pragma unroll
    for (int o = 16; o; o >>= 1) s += __shfl_xor_sync(0xffffffffu, s, o);
    if (lane == 0) sm[wd] = s;
    __syncthreads();
    if (tid < 32) {
        float t = sm[tid];
        #pragma unroll
        for (int o = 16; o; o >>= 1) t += __shfl_xor_sync(0xffffffffu, t, o);
        if (tid == 0) s_b = t;
    }
    __syncthreads();
    const float inv = 1.0f / s_b;
    #pragma unroll
    for (int i = 0; i < 4; ++i) row[tid + (i << 10)] = v[i] * inv;
}

// ---------------------------------------------------------------------------
// K3/K4: context
// ---------------------------------------------------------------------------
__global__ void cpart_kernel(const float* __restrict__ X,
                             const float* __restrict__ w) {
    const int c = blockIdx.x, b = blockIdx.y, e = threadIdx.x;
    const float* xb = X + ((size_t)b * T_ + (size_t)c * 512) * E_ + e;
    const float* wb = w + (size_t)b * T_ + (size_t)c * 512;
    float a[8] = {0,0,0,0,0,0,0,0};
    #pragma unroll 2
    for (int t = 0; t < 512; t += 8) {
        #pragma unroll
        for (int u = 0; u < 8; ++u)
            a[u] = fmaf(wb[t + u], xb[(size_t)(t + u) * E_], a[u]);
    }
    g_cpart[((size_t)c * B_ + b) * E_ + e] =
        ((a[0] + a[1]) + (a[2] + a[3])) + ((a[4] + a[5]) + (a[6] + a[7]));
}

__global__ void creduce_kernel(float* __restrict__ ctx) {
    int i = blockIdx.x * blockDim.x + threadIdx.x;
    int b = i >> 9, e = i & 511;
    float s = 0.f;
    #pragma unroll
    for (int c = 0; c < 8; ++c)
        s += g_cpart[((size_t)c * B_ + b) * E_ + e];
    ctx[i] = s;
}

// ---------------------------------------------------------------------------
extern "C" void kernel_launch(void* const* d_in, const int* in_sizes, int n_in,
                              void* d_out, int out_size) {
    const float* X     = (const float*)d_in[0];
    const float* dec   = (const float*)d_in[1];
    const float* W_enc = (const float*)d_in[2];
    const float* b_enc = (const float*)d_in[3];
    const float* W_dec = (const float*)d_in[4];
    const float* v_att = (const float*)d_in[5];
    const float* b_att = (const float*)d_in[6];

    float* ctx     = (float*)d_out;
    float* weights = (float*)d_out + B_ * E_;

    cudaFuncSetAttribute(scores_mma_kernel,
                         cudaFuncAttributeMaxDynamicSharedMemorySize, SMEM_TOTAL);

    convert_w_kernel<<<E_, A_>>>(W_enc);
    dproj_kernel<<<B_, A_>>>(dec, W_dec, b_enc);

    dim3 g1(T_ / 128, B_);
    scores_mma_kernel<<<g1, 256, SMEM_TOTAL>>>(X, v_att, b_att, weights);

    softmax_kernel<<<B_, 1024>>>(weights);

    dim3 g3(8, B_);
    cpart_kernel<<<g3, E_>>>(X, weights);
    creduce_kernel<<<(B_ * E_) / 256, 256>>>(ctx);
}